// round 1
// baseline (speedup 1.0000x reference)
#include <cuda_runtime.h>
#include <math.h>

// Problem constants
#define NT   4096          // B*S tokens
#define DMODEL 1024        // D = H*DQK = H*DV
#define NHEAD 16
#define HD   64            // head dim (DQK == DV)
#define SEQ  2048
#define BATCH 2

// Scratch (no cudaMalloc allowed)
__device__ float g_Q[(size_t)NT * DMODEL];
__device__ float g_K[(size_t)NT * DMODEL];
__device__ float g_V[(size_t)NT * DMODEL];
__device__ float g_A[(size_t)NT * DMODEL];

// ---------------------------------------------------------------------------
// Tiled fp32 GEMM: C[M,N] = A[M,K] @ B[K,N]
// 64x64 tile, k-tile 16, 16x16 threads, 4x4 microtile per thread.
// ---------------------------------------------------------------------------
#define TM 64
#define TN 64
#define TK 16

__global__ __launch_bounds__(256) void gemm_kernel(
    const float* __restrict__ A, const float* __restrict__ B,
    float* __restrict__ C, int M, int N, int K)
{
    __shared__ float As[TK][TM];
    __shared__ float Bs[TK][TN];
    const int tx = threadIdx.x;       // 0..15
    const int ty = threadIdx.y;       // 0..15
    const int tid = ty * 16 + tx;
    const int m0 = blockIdx.y * TM;
    const int n0 = blockIdx.x * TN;

    float acc[4][4];
    #pragma unroll
    for (int i = 0; i < 4; i++)
        #pragma unroll
        for (int j = 0; j < 4; j++) acc[i][j] = 0.0f;

    for (int k0 = 0; k0 < K; k0 += TK) {
        // Load A tile (TM x TK) transposed into As[k][m]
        #pragma unroll
        for (int i = tid; i < TM * TK; i += 256) {
            int m = i / TK, k = i % TK;
            As[k][m] = A[(size_t)(m0 + m) * K + (k0 + k)];
        }
        // Load B tile (TK x TN) into Bs[k][n]
        #pragma unroll
        for (int i = tid; i < TK * TN; i += 256) {
            int k = i / TN, n = i % TN;
            Bs[k][n] = B[(size_t)(k0 + k) * N + (n0 + n)];
        }
        __syncthreads();

        #pragma unroll
        for (int kk = 0; kk < TK; kk++) {
            float a[4], b[4];
            #pragma unroll
            for (int i = 0; i < 4; i++) a[i] = As[kk][ty * 4 + i];
            #pragma unroll
            for (int j = 0; j < 4; j++) b[j] = Bs[kk][tx * 4 + j];
            #pragma unroll
            for (int i = 0; i < 4; i++)
                #pragma unroll
                for (int j = 0; j < 4; j++)
                    acc[i][j] = fmaf(a[i], b[j], acc[i][j]);
        }
        __syncthreads();
    }

    #pragma unroll
    for (int i = 0; i < 4; i++)
        #pragma unroll
        for (int j = 0; j < 4; j++)
            C[(size_t)(m0 + ty * 4 + i) * N + (n0 + tx * 4 + j)] = acc[i][j];
}

// ---------------------------------------------------------------------------
// Causal flash attention, fp32.
// Grid: (S/64, H, B). Block: 64 threads; thread t owns query row t of the tile.
// Q,K,V,O layout: [token, h*HD + d] (token = b*SEQ + s), i.e. [NT, DMODEL].
// ---------------------------------------------------------------------------
#define QT 64
#define KT 64

__global__ __launch_bounds__(64) void attn_kernel(
    const float* __restrict__ Q, const float* __restrict__ K,
    const float* __restrict__ V, float* __restrict__ O)
{
    const int qt = blockIdx.x;
    const int h  = blockIdx.y;
    const int b  = blockIdx.z;
    const int row = threadIdx.x;            // 0..63
    const int qg  = qt * QT + row;          // query pos within sequence
    const size_t tok0 = (size_t)b * SEQ;

    __shared__ float Ksh[KT][HD];
    __shared__ float Vsh[KT][HD];
    __shared__ float Ssh[QT][KT + 1];       // scores, +1 pad: conflict-free

    // q row, pre-scaled
    float q[HD];
    {
        const float* qp = Q + (tok0 + qg) * DMODEL + h * HD;
        #pragma unroll
        for (int d = 0; d < HD; d++) q[d] = qp[d] * 0.125f;  // 1/sqrt(64)
    }

    float acc[HD];
    #pragma unroll
    for (int d = 0; d < HD; d++) acc[d] = 0.0f;
    float m = -INFINITY, l = 0.0f;

    for (int kt = 0; kt <= qt; kt++) {
        __syncthreads();   // previous tile fully consumed
        // Cooperative K/V tile load (float4), 16 iters/thread
        #pragma unroll
        for (int i = row; i < KT * (HD / 4); i += 64) {
            int r  = i / (HD / 4);
            int c4 = i % (HD / 4);
            const float4* kp = (const float4*)(K + (tok0 + kt * KT + r) * DMODEL + h * HD) + c4;
            const float4* vp = (const float4*)(V + (tok0 + kt * KT + r) * DMODEL + h * HD) + c4;
            ((float4*)&Ksh[r][0])[c4] = *kp;
            ((float4*)&Vsh[r][0])[c4] = *vp;
        }
        __syncthreads();

        // Scores for this thread's query row
        float tile_max = -INFINITY;
        #pragma unroll 1
        for (int j = 0; j < KT; j++) {
            float s = 0.0f;
            #pragma unroll
            for (int d = 0; d < HD; d += 4) {
                float4 kv = *((const float4*)&Ksh[j][d]);
                s = fmaf(q[d],     kv.x, s);
                s = fmaf(q[d + 1], kv.y, s);
                s = fmaf(q[d + 2], kv.z, s);
                s = fmaf(q[d + 3], kv.w, s);
            }
            if (kt * KT + j > qg) s = -INFINITY;   // causal mask
            Ssh[row][j] = s;
            tile_max = fmaxf(tile_max, s);
        }

        const float m_new = fmaxf(m, tile_max);
        const float corr  = __expf(m - m_new);     // 0 when m == -inf
        l *= corr;
        #pragma unroll
        for (int d = 0; d < HD; d++) acc[d] *= corr;

        #pragma unroll 1
        for (int j = 0; j < KT; j++) {
            const float p = __expf(Ssh[row][j] - m_new);  // masked -> 0
            l += p;
            #pragma unroll
            for (int d = 0; d < HD; d += 4) {
                float4 vv = *((const float4*)&Vsh[j][d]);
                acc[d]     = fmaf(p, vv.x, acc[d]);
                acc[d + 1] = fmaf(p, vv.y, acc[d + 1]);
                acc[d + 2] = fmaf(p, vv.z, acc[d + 2]);
                acc[d + 3] = fmaf(p, vv.w, acc[d + 3]);
            }
        }
        m = m_new;
    }

    const float inv_l = 1.0f / l;
    float* op = O + (tok0 + qg) * DMODEL + h * HD;
    #pragma unroll
    for (int d = 0; d < HD; d++) op[d] = acc[d] * inv_l;
}

// ---------------------------------------------------------------------------
// Launch
// ---------------------------------------------------------------------------
extern "C" void kernel_launch(void* const* d_in, const int* in_sizes, int n_in,
                              void* d_out, int out_size)
{
    const float* x   = (const float*)d_in[0];
    const float* W_q = (const float*)d_in[1];
    const float* W_k = (const float*)d_in[2];
    const float* W_v = (const float*)d_in[3];
    const float* W_o = (const float*)d_in[4];
    float* out = (float*)d_out;

    float *Qp, *Kp, *Vp, *Ap;
    cudaGetSymbolAddress((void**)&Qp, g_Q);
    cudaGetSymbolAddress((void**)&Kp, g_K);
    cudaGetSymbolAddress((void**)&Vp, g_V);
    cudaGetSymbolAddress((void**)&Ap, g_A);

    dim3 gblk(16, 16);
    dim3 ggrd(DMODEL / TN, NT / TM);   // (16, 64)

    gemm_kernel<<<ggrd, gblk>>>(x, W_q, Qp, NT, DMODEL, DMODEL);
    gemm_kernel<<<ggrd, gblk>>>(x, W_k, Kp, NT, DMODEL, DMODEL);
    gemm_kernel<<<ggrd, gblk>>>(x, W_v, Vp, NT, DMODEL, DMODEL);

    dim3 agrd(SEQ / QT, NHEAD, BATCH); // (32, 16, 2)
    attn_kernel<<<agrd, 64>>>(Qp, Kp, Vp, Ap);

    gemm_kernel<<<ggrd, gblk>>>(Ap, W_o, out, NT, DMODEL, DMODEL);
}

// round 2
// speedup vs baseline: 1.3938x; 1.3938x over previous
#include <cuda_runtime.h>
#include <math.h>
#include <stdint.h>

// Problem constants
#define NT     4096        // B*S tokens
#define DMODEL 1024
#define NHEAD  16
#define HD     64
#define SEQ    2048
#define BATCH  2

// Scratch (no cudaMalloc allowed)
__device__ float g_Q[(size_t)NT * DMODEL];
__device__ float g_K[(size_t)NT * DMODEL];
__device__ float g_V[(size_t)NT * DMODEL];
__device__ float g_A[(size_t)NT * DMODEL];

// ---------------------------------------------------------------------------
// 3xTF32 tensor-core GEMM: C[M,N] = A[M,K] @ B[K,N], fp32-class accuracy.
// Block tile 128x128, k-tile 32. 8 warps, warp tile 64x32 (4x4 m16n8k8 tiles).
// A/B split into tf32 hi/lo at smem-fill time; 3 MMAs (hh, hl, lh) per tile.
// ---------------------------------------------------------------------------
#define BM 128
#define BN 128
#define BK 32
#define ASTRIDE 36       // pad: bank-conflict-free frag loads (36%32=4)
#define BSTRIDE 136      // pad: (136%32=8)
#define AS_SZ (BM * ASTRIDE)   // 4608 floats
#define BS_SZ (BK * BSTRIDE)   // 4352 floats
#define GEMM_SMEM ((2 * AS_SZ + 2 * BS_SZ) * 4)   // 71680 bytes

__device__ __forceinline__ float tf32_hi(float x) {
    return __uint_as_float(__float_as_uint(x) & 0xFFFFE000u);
}

__device__ __forceinline__ void mma_tf32(float c[4], uint32_t a0, uint32_t a1,
                                         uint32_t a2, uint32_t a3,
                                         uint32_t b0, uint32_t b1) {
    asm volatile(
        "mma.sync.aligned.m16n8k8.row.col.f32.tf32.tf32.f32 "
        "{%0,%1,%2,%3}, {%4,%5,%6,%7}, {%8,%9}, {%0,%1,%2,%3};\n"
        : "+f"(c[0]), "+f"(c[1]), "+f"(c[2]), "+f"(c[3])
        : "r"(a0), "r"(a1), "r"(a2), "r"(a3), "r"(b0), "r"(b1));
}

__global__ __launch_bounds__(256) void gemm_tf32(
    const float* __restrict__ A, const float* __restrict__ B,
    float* __restrict__ C, int M, int N, int K)
{
    extern __shared__ float sm[];
    float* As_h = sm;
    float* As_l = As_h + AS_SZ;
    float* Bs_h = As_l + AS_SZ;
    float* Bs_l = Bs_h + BS_SZ;

    const int tid  = threadIdx.x;
    const int lane = tid & 31;
    const int warp = tid >> 5;
    const int wm = (warp >> 2) * 64;   // 0 / 64
    const int wn = (warp & 3) * 32;    // 0..96
    const int m0 = blockIdx.y * BM;
    const int n0 = blockIdx.x * BN;

    float c[4][4][4];
    #pragma unroll
    for (int mt = 0; mt < 4; mt++)
        #pragma unroll
        for (int nt = 0; nt < 4; nt++)
            #pragma unroll
            for (int i = 0; i < 4; i++) c[mt][nt][i] = 0.0f;

    float4 aR[4], bR[4];

    // ---- global loads into registers ----
    auto ldg_tile = [&](int k0) {
        #pragma unroll
        for (int i = 0; i < 4; i++) {
            int idx = tid + i * 256;                 // 0..1023
            int m = idx >> 3, kq = (idx & 7) << 2;   // A: 128 x 32
            aR[i] = *(const float4*)(A + (size_t)(m0 + m) * K + k0 + kq);
        }
        #pragma unroll
        for (int i = 0; i < 4; i++) {
            int idx = tid + i * 256;
            int k = idx >> 5, n4 = (idx & 31) << 2;  // B: 32 x 128
            bR[i] = *(const float4*)(B + (size_t)(k0 + k) * N + n0 + n4);
        }
    };

    // ---- split + store to smem ----
    auto sts_tile = [&]() {
        #pragma unroll
        for (int i = 0; i < 4; i++) {
            int idx = tid + i * 256;
            int m = idx >> 3, kq = (idx & 7) << 2;
            float4 v = aR[i];
            float4 h, l;
            h.x = tf32_hi(v.x); l.x = tf32_hi(v.x - h.x);
            h.y = tf32_hi(v.y); l.y = tf32_hi(v.y - h.y);
            h.z = tf32_hi(v.z); l.z = tf32_hi(v.z - h.z);
            h.w = tf32_hi(v.w); l.w = tf32_hi(v.w - h.w);
            *(float4*)(As_h + m * ASTRIDE + kq) = h;
            *(float4*)(As_l + m * ASTRIDE + kq) = l;
        }
        #pragma unroll
        for (int i = 0; i < 4; i++) {
            int idx = tid + i * 256;
            int k = idx >> 5, n4 = (idx & 31) << 2;
            float4 v = bR[i];
            float4 h, l;
            h.x = tf32_hi(v.x); l.x = tf32_hi(v.x - h.x);
            h.y = tf32_hi(v.y); l.y = tf32_hi(v.y - h.y);
            h.z = tf32_hi(v.z); l.z = tf32_hi(v.z - h.z);
            h.w = tf32_hi(v.w); l.w = tf32_hi(v.w - h.w);
            *(float4*)(Bs_h + k * BSTRIDE + n4) = h;
            *(float4*)(Bs_l + k * BSTRIDE + n4) = l;
        }
    };

    const int NKI = K / BK;
    ldg_tile(0);

    #pragma unroll 1
    for (int kt = 0; kt < NKI; kt++) {
        sts_tile();
        __syncthreads();
        if (kt + 1 < NKI) ldg_tile((kt + 1) * BK);   // overlap with compute

        #pragma unroll
        for (int ks = 0; ks < 4; ks++) {
            const int kc = ks * 8 + (lane & 3);
            const int rA = lane >> 2;

            uint32_t ah[4][4], al[4][4];
            #pragma unroll
            for (int mt = 0; mt < 4; mt++) {
                int m = wm + mt * 16 + rA;
                ah[mt][0] = __float_as_uint(As_h[m * ASTRIDE + kc]);
                ah[mt][1] = __float_as_uint(As_h[(m + 8) * ASTRIDE + kc]);
                ah[mt][2] = __float_as_uint(As_h[m * ASTRIDE + kc + 4]);
                ah[mt][3] = __float_as_uint(As_h[(m + 8) * ASTRIDE + kc + 4]);
                al[mt][0] = __float_as_uint(As_l[m * ASTRIDE + kc]);
                al[mt][1] = __float_as_uint(As_l[(m + 8) * ASTRIDE + kc]);
                al[mt][2] = __float_as_uint(As_l[m * ASTRIDE + kc + 4]);
                al[mt][3] = __float_as_uint(As_l[(m + 8) * ASTRIDE + kc + 4]);
            }
            uint32_t bh[4][2], bl[4][2];
            #pragma unroll
            for (int nt = 0; nt < 4; nt++) {
                int n = wn + nt * 8 + rA;
                bh[nt][0] = __float_as_uint(Bs_h[kc * BSTRIDE + n]);
                bh[nt][1] = __float_as_uint(Bs_h[(kc + 4) * BSTRIDE + n]);
                bl[nt][0] = __float_as_uint(Bs_l[kc * BSTRIDE + n]);
                bl[nt][1] = __float_as_uint(Bs_l[(kc + 4) * BSTRIDE + n]);
            }
            #pragma unroll
            for (int mt = 0; mt < 4; mt++)
                #pragma unroll
                for (int nt = 0; nt < 4; nt++) {
                    mma_tf32(c[mt][nt], ah[mt][0], ah[mt][1], ah[mt][2], ah[mt][3],
                             bh[nt][0], bh[nt][1]);
                    mma_tf32(c[mt][nt], ah[mt][0], ah[mt][1], ah[mt][2], ah[mt][3],
                             bl[nt][0], bl[nt][1]);
                    mma_tf32(c[mt][nt], al[mt][0], al[mt][1], al[mt][2], al[mt][3],
                             bh[nt][0], bh[nt][1]);
                }
        }
        __syncthreads();
    }

    // epilogue
    #pragma unroll
    for (int mt = 0; mt < 4; mt++)
        #pragma unroll
        for (int nt = 0; nt < 4; nt++) {
            int m = m0 + wm + mt * 16 + (lane >> 2);
            int n = n0 + wn + nt * 8 + (lane & 3) * 2;
            *(float2*)(C + (size_t)m * N + n)       = make_float2(c[mt][nt][0], c[mt][nt][1]);
            *(float2*)(C + (size_t)(m + 8) * N + n) = make_float2(c[mt][nt][2], c[mt][nt][3]);
        }
}

// ---------------------------------------------------------------------------
// Causal flash attention, fp32, lane-pair split over head dim.
// 128 threads: thread (2r+h) handles query row r, dims [h*32, h*32+32).
// Score halves combined with shfl_xor(.,1).
// ---------------------------------------------------------------------------
#define QT 64
#define SSTRIDE 65
#define ATTN_SMEM ((64 * 64 * 2 + 64 * SSTRIDE) * 4)   // 49408 bytes

__global__ __launch_bounds__(128) void attn_kernel2(
    const float* __restrict__ Q, const float* __restrict__ K,
    const float* __restrict__ V, float* __restrict__ O)
{
    extern __shared__ float s[];
    float* Ksh = s;                // [64][64]
    float* Vsh = s + 64 * 64;      // [64][64]
    float* Ssh = s + 2 * 64 * 64;  // [64][65]

    const int tid  = threadIdx.x;
    const int row  = tid >> 1;
    const int half = tid & 1;
    const int d0   = half * 32;
    const int qt = blockIdx.x, h = blockIdx.y, b = blockIdx.z;
    const int qg = qt * QT + row;
    const size_t tok0 = (size_t)b * SEQ;

    float q[32];
    {
        const float* qp = Q + (tok0 + qg) * DMODEL + h * HD + d0;
        #pragma unroll
        for (int d = 0; d < 32; d++) q[d] = qp[d] * 0.125f;  // 1/sqrt(64)
    }

    float acc[32];
    #pragma unroll
    for (int d = 0; d < 32; d++) acc[d] = 0.0f;
    float m = -INFINITY, l = 0.0f;

    for (int kt = 0; kt <= qt; kt++) {
        __syncthreads();   // previous tile fully consumed
        #pragma unroll
        for (int i = tid; i < 64 * 16; i += 128) {
            int r = i >> 4, c4 = (i & 15) << 2;
            const size_t base = (tok0 + kt * 64 + r) * DMODEL + h * HD + c4;
            *(float4*)(Ksh + r * 64 + c4) = *(const float4*)(K + base);
            *(float4*)(Vsh + r * 64 + c4) = *(const float4*)(V + base);
        }
        __syncthreads();

        float tile_max = -INFINITY;
        #pragma unroll 4
        for (int j = 0; j < 64; j++) {
            float sc = 0.0f;
            #pragma unroll
            for (int d = 0; d < 32; d += 4) {
                float4 kv = *(const float4*)(Ksh + j * 64 + d0 + d);
                sc = fmaf(q[d],     kv.x, sc);
                sc = fmaf(q[d + 1], kv.y, sc);
                sc = fmaf(q[d + 2], kv.z, sc);
                sc = fmaf(q[d + 3], kv.w, sc);
            }
            sc += __shfl_xor_sync(0xffffffffu, sc, 1);   // combine halves
            if (kt * 64 + j > qg) sc = -INFINITY;        // causal
            if (half == 0) Ssh[row * SSTRIDE + j] = sc;
            tile_max = fmaxf(tile_max, sc);
        }
        __syncwarp();

        const float m_new = fmaxf(m, tile_max);
        const float corr  = __expf(m - m_new);
        l *= corr;
        #pragma unroll
        for (int d = 0; d < 32; d++) acc[d] *= corr;

        #pragma unroll 4
        for (int j = 0; j < 64; j++) {
            const float p = __expf(Ssh[row * SSTRIDE + j] - m_new);
            l += p;
            #pragma unroll
            for (int d = 0; d < 32; d += 4) {
                float4 vv = *(const float4*)(Vsh + j * 64 + d0 + d);
                acc[d]     = fmaf(p, vv.x, acc[d]);
                acc[d + 1] = fmaf(p, vv.y, acc[d + 1]);
                acc[d + 2] = fmaf(p, vv.z, acc[d + 2]);
                acc[d + 3] = fmaf(p, vv.w, acc[d + 3]);
            }
        }
        m = m_new;
    }

    const float inv_l = 1.0f / l;
    float* op = O + (tok0 + qg) * DMODEL + h * HD + d0;
    #pragma unroll
    for (int d = 0; d < 32; d += 4) {
        float4 o4 = make_float4(acc[d] * inv_l, acc[d + 1] * inv_l,
                                acc[d + 2] * inv_l, acc[d + 3] * inv_l);
        *(float4*)(op + d) = o4;
    }
}

// ---------------------------------------------------------------------------
// Launch
// ---------------------------------------------------------------------------
extern "C" void kernel_launch(void* const* d_in, const int* in_sizes, int n_in,
                              void* d_out, int out_size)
{
    const float* x   = (const float*)d_in[0];
    const float* W_q = (const float*)d_in[1];
    const float* W_k = (const float*)d_in[2];
    const float* W_v = (const float*)d_in[3];
    const float* W_o = (const float*)d_in[4];
    float* out = (float*)d_out;

    float *Qp, *Kp, *Vp, *Ap;
    cudaGetSymbolAddress((void**)&Qp, g_Q);
    cudaGetSymbolAddress((void**)&Kp, g_K);
    cudaGetSymbolAddress((void**)&Vp, g_V);
    cudaGetSymbolAddress((void**)&Ap, g_A);

    cudaFuncSetAttribute(gemm_tf32, cudaFuncAttributeMaxDynamicSharedMemorySize, GEMM_SMEM);
    cudaFuncSetAttribute(attn_kernel2, cudaFuncAttributeMaxDynamicSharedMemorySize, ATTN_SMEM);

    dim3 ggrd(DMODEL / BN, NT / BM);   // (8, 32)

    gemm_tf32<<<ggrd, 256, GEMM_SMEM>>>(x, W_q, Qp, NT, DMODEL, DMODEL);
    gemm_tf32<<<ggrd, 256, GEMM_SMEM>>>(x, W_k, Kp, NT, DMODEL, DMODEL);
    gemm_tf32<<<ggrd, 256, GEMM_SMEM>>>(x, W_v, Vp, NT, DMODEL, DMODEL);

    dim3 agrd(SEQ / QT, NHEAD, BATCH); // (32, 16, 2)
    attn_kernel2<<<agrd, 128, ATTN_SMEM>>>(Qp, Kp, Vp, Ap);

    gemm_tf32<<<ggrd, 256, GEMM_SMEM>>>(Ap, W_o, out, NT, DMODEL, DMODEL);
}

// round 5
// speedup vs baseline: 2.9455x; 2.1133x over previous
#include <cuda_runtime.h>
#include <math.h>
#include <stdint.h>

// Problem constants
#define NT     4096        // B*S tokens
#define DMODEL 1024
#define NHEAD  16
#define HD     64
#define SEQ    2048
#define BATCH  2

// Scratch (no cudaMalloc allowed)
__device__ float g_Q[(size_t)NT * DMODEL];
__device__ float g_K[(size_t)NT * DMODEL];
__device__ float g_V[(size_t)NT * DMODEL];
__device__ float g_A[(size_t)NT * DMODEL];

__device__ __forceinline__ float f2tf(float x) {
    uint32_t r; asm("cvt.rna.tf32.f32 %0, %1;" : "=r"(r) : "f"(x));
    return __uint_as_float(r);
}

__device__ __forceinline__ void mma_tf32(float c[4], uint32_t a0, uint32_t a1,
                                         uint32_t a2, uint32_t a3,
                                         uint32_t b0, uint32_t b1) {
    asm volatile(
        "mma.sync.aligned.m16n8k8.row.col.f32.tf32.tf32.f32 "
        "{%0,%1,%2,%3}, {%4,%5,%6,%7}, {%8,%9}, {%0,%1,%2,%3};\n"
        : "+f"(c[0]), "+f"(c[1]), "+f"(c[2]), "+f"(c[3])
        : "r"(a0), "r"(a1), "r"(a2), "r"(a3), "r"(b0), "r"(b1));
}

// ---------------------------------------------------------------------------
// 3xTF32 tensor-core GEMM (unchanged): C[M,N] = A[M,K] @ B[K,N]
// ---------------------------------------------------------------------------
#define BM 128
#define BN 128
#define BK 32
#define ASTRIDE 36
#define BSTRIDE 136
#define AS_SZ (BM * ASTRIDE)
#define BS_SZ (BK * BSTRIDE)
#define GEMM_SMEM ((2 * AS_SZ + 2 * BS_SZ) * 4)

__device__ __forceinline__ float tf32_hi(float x) {
    return __uint_as_float(__float_as_uint(x) & 0xFFFFE000u);
}

__global__ __launch_bounds__(256) void gemm_tf32(
    const float* __restrict__ A, const float* __restrict__ B,
    float* __restrict__ C, int M, int N, int K)
{
    extern __shared__ float sm[];
    float* As_h = sm;
    float* As_l = As_h + AS_SZ;
    float* Bs_h = As_l + AS_SZ;
    float* Bs_l = Bs_h + BS_SZ;

    const int tid  = threadIdx.x;
    const int lane = tid & 31;
    const int warp = tid >> 5;
    const int wm = (warp >> 2) * 64;
    const int wn = (warp & 3) * 32;
    const int m0 = blockIdx.y * BM;
    const int n0 = blockIdx.x * BN;

    float c[4][4][4];
    #pragma unroll
    for (int mt = 0; mt < 4; mt++)
        #pragma unroll
        for (int nt = 0; nt < 4; nt++)
            #pragma unroll
            for (int i = 0; i < 4; i++) c[mt][nt][i] = 0.0f;

    float4 aR[4], bR[4];

    auto ldg_tile = [&](int k0) {
        #pragma unroll
        for (int i = 0; i < 4; i++) {
            int idx = tid + i * 256;
            int m = idx >> 3, kq = (idx & 7) << 2;
            aR[i] = *(const float4*)(A + (size_t)(m0 + m) * K + k0 + kq);
        }
        #pragma unroll
        for (int i = 0; i < 4; i++) {
            int idx = tid + i * 256;
            int k = idx >> 5, n4 = (idx & 31) << 2;
            bR[i] = *(const float4*)(B + (size_t)(k0 + k) * N + n0 + n4);
        }
    };

    auto sts_tile = [&]() {
        #pragma unroll
        for (int i = 0; i < 4; i++) {
            int idx = tid + i * 256;
            int m = idx >> 3, kq = (idx & 7) << 2;
            float4 v = aR[i];
            float4 h, l;
            h.x = tf32_hi(v.x); l.x = tf32_hi(v.x - h.x);
            h.y = tf32_hi(v.y); l.y = tf32_hi(v.y - h.y);
            h.z = tf32_hi(v.z); l.z = tf32_hi(v.z - h.z);
            h.w = tf32_hi(v.w); l.w = tf32_hi(v.w - h.w);
            *(float4*)(As_h + m * ASTRIDE + kq) = h;
            *(float4*)(As_l + m * ASTRIDE + kq) = l;
        }
        #pragma unroll
        for (int i = 0; i < 4; i++) {
            int idx = tid + i * 256;
            int k = idx >> 5, n4 = (idx & 31) << 2;
            float4 v = bR[i];
            float4 h, l;
            h.x = tf32_hi(v.x); l.x = tf32_hi(v.x - h.x);
            h.y = tf32_hi(v.y); l.y = tf32_hi(v.y - h.y);
            h.z = tf32_hi(v.z); l.z = tf32_hi(v.z - h.z);
            h.w = tf32_hi(v.w); l.w = tf32_hi(v.w - h.w);
            *(float4*)(Bs_h + k * BSTRIDE + n4) = h;
            *(float4*)(Bs_l + k * BSTRIDE + n4) = l;
        }
    };

    const int NKI = K / BK;
    ldg_tile(0);

    #pragma unroll 1
    for (int kt = 0; kt < NKI; kt++) {
        sts_tile();
        __syncthreads();
        if (kt + 1 < NKI) ldg_tile((kt + 1) * BK);

        #pragma unroll
        for (int ks = 0; ks < 4; ks++) {
            const int kc = ks * 8 + (lane & 3);
            const int rA = lane >> 2;

            uint32_t ah[4][4], al[4][4];
            #pragma unroll
            for (int mt = 0; mt < 4; mt++) {
                int m = wm + mt * 16 + rA;
                ah[mt][0] = __float_as_uint(As_h[m * ASTRIDE + kc]);
                ah[mt][1] = __float_as_uint(As_h[(m + 8) * ASTRIDE + kc]);
                ah[mt][2] = __float_as_uint(As_h[m * ASTRIDE + kc + 4]);
                ah[mt][3] = __float_as_uint(As_h[(m + 8) * ASTRIDE + kc + 4]);
                al[mt][0] = __float_as_uint(As_l[m * ASTRIDE + kc]);
                al[mt][1] = __float_as_uint(As_l[(m + 8) * ASTRIDE + kc]);
                al[mt][2] = __float_as_uint(As_l[m * ASTRIDE + kc + 4]);
                al[mt][3] = __float_as_uint(As_l[(m + 8) * ASTRIDE + kc + 4]);
            }
            uint32_t bh[4][2], bl[4][2];
            #pragma unroll
            for (int nt = 0; nt < 4; nt++) {
                int n = wn + nt * 8 + rA;
                bh[nt][0] = __float_as_uint(Bs_h[kc * BSTRIDE + n]);
                bh[nt][1] = __float_as_uint(Bs_h[(kc + 4) * BSTRIDE + n]);
                bl[nt][0] = __float_as_uint(Bs_l[kc * BSTRIDE + n]);
                bl[nt][1] = __float_as_uint(Bs_l[(kc + 4) * BSTRIDE + n]);
            }
            #pragma unroll
            for (int mt = 0; mt < 4; mt++)
                #pragma unroll
                for (int nt = 0; nt < 4; nt++) {
                    mma_tf32(c[mt][nt], ah[mt][0], ah[mt][1], ah[mt][2], ah[mt][3],
                             bh[nt][0], bh[nt][1]);
                    mma_tf32(c[mt][nt], ah[mt][0], ah[mt][1], ah[mt][2], ah[mt][3],
                             bl[nt][0], bl[nt][1]);
                    mma_tf32(c[mt][nt], al[mt][0], al[mt][1], al[mt][2], al[mt][3],
                             bh[nt][0], bh[nt][1]);
                }
        }
        __syncthreads();
    }

    #pragma unroll
    for (int mt = 0; mt < 4; mt++)
        #pragma unroll
        for (int nt = 0; nt < 4; nt++) {
            int m = m0 + wm + mt * 16 + (lane >> 2);
            int n = n0 + wn + nt * 8 + (lane & 3) * 2;
            *(float2*)(C + (size_t)m * N + n)       = make_float2(c[mt][nt][0], c[mt][nt][1]);
            *(float2*)(C + (size_t)(m + 8) * N + n) = make_float2(c[mt][nt][2], c[mt][nt][3]);
        }
}

// ---------------------------------------------------------------------------
// Tensor-core causal flash attention (tf32 mma.sync).
// Block: 4 warps; warp w owns query rows [w*16, w*16+16) of a 64-row q-tile.
// Each block processes q-tiles bx and 31-bx (uniform 33 K-tiles of work).
// Tile stride 68 (= 64 data + 4 pad; 68 % 32 == 4 -> conflict-free b-frags).
// ---------------------------------------------------------------------------
#define KTS 68
#define ATTN_SMEM ((2 * 64 * KTS + 4 * 16 * KTS) * 4)   // 52224 bytes

__global__ __launch_bounds__(128) void attn_mma(
    const float* __restrict__ Q, const float* __restrict__ K,
    const float* __restrict__ V, float* __restrict__ O)
{
    extern __shared__ float smem[];
    float* Kt = smem;                  // K^T tile: [d=64][key<=64], stride KTS
    float* Vs = Kt + 64 * KTS;         // V tile:   [key=64][d<=64], stride KTS
    float* Ps = Vs + 64 * KTS;         // per-warp P: [4][16][<=64], stride KTS

    const int tid  = threadIdx.x;
    const int lane = tid & 31, warp = tid >> 5;
    const int g = lane >> 2, t = lane & 3;
    const int h = blockIdx.y, b = blockIdx.z;
    const size_t tok0 = (size_t)b * SEQ;
    float* Pw = Ps + warp * 16 * KTS;

    #pragma unroll 1
    for (int pass = 0; pass < 2; pass++) {
        const int qt = pass ? (31 - (int)blockIdx.x) : (int)blockIdx.x;
        const int qrow = qt * 64 + warp * 16 + g;         // row of c0/c1
        const float* qb = Q + (tok0 + qrow) * DMODEL + h * HD;

        // Q fragments (tf32, pre-scaled by 1/sqrt(64)), resident in registers
        uint32_t qf[8][4];
        #pragma unroll
        for (int kc = 0; kc < 8; kc++) {
            qf[kc][0] = __float_as_uint(f2tf(qb[kc * 8 + t] * 0.125f));
            qf[kc][1] = __float_as_uint(f2tf(qb[8 * DMODEL + kc * 8 + t] * 0.125f));
            qf[kc][2] = __float_as_uint(f2tf(qb[kc * 8 + t + 4] * 0.125f));
            qf[kc][3] = __float_as_uint(f2tf(qb[8 * DMODEL + kc * 8 + t + 4] * 0.125f));
        }

        float o[8][4];
        #pragma unroll
        for (int nt = 0; nt < 8; nt++)
            #pragma unroll
            for (int i = 0; i < 4; i++) o[nt][i] = 0.0f;
        float m0 = -INFINITY, m1 = -INFINITY, l0 = 0.0f, l1 = 0.0f;

        #pragma unroll 1
        for (int kt = 0; kt <= qt; kt++) {
            __syncthreads();   // previous tile fully consumed
            // Cooperative K/V tile load + tf32 convert; K transposed.
            #pragma unroll
            for (int i = tid; i < 64 * 16; i += 128) {
                int r = i >> 4, c4 = (i & 15) << 2;
                const size_t base = (tok0 + kt * 64 + r) * DMODEL + h * HD + c4;
                float4 kv = *(const float4*)(K + base);
                Kt[(c4 + 0) * KTS + r] = f2tf(kv.x);
                Kt[(c4 + 1) * KTS + r] = f2tf(kv.y);
                Kt[(c4 + 2) * KTS + r] = f2tf(kv.z);
                Kt[(c4 + 3) * KTS + r] = f2tf(kv.w);
                float4 vv = *(const float4*)(V + base);
                vv.x = f2tf(vv.x); vv.y = f2tf(vv.y);
                vv.z = f2tf(vv.z); vv.w = f2tf(vv.w);
                *(float4*)(Vs + r * KTS + c4) = vv;
            }
            __syncthreads();

            // S = Q @ K^T
            float sc[8][4];
            #pragma unroll
            for (int nt = 0; nt < 8; nt++)
                #pragma unroll
                for (int i = 0; i < 4; i++) sc[nt][i] = 0.0f;
            #pragma unroll
            for (int kc = 0; kc < 8; kc++) {
                const float* kb0 = Kt + (kc * 8 + t) * KTS + g;
                const float* kb1 = Kt + (kc * 8 + t + 4) * KTS + g;
                #pragma unroll
                for (int nt = 0; nt < 8; nt++) {
                    mma_tf32(sc[nt], qf[kc][0], qf[kc][1], qf[kc][2], qf[kc][3],
                             __float_as_uint(kb0[nt * 8]),
                             __float_as_uint(kb1[nt * 8]));
                }
            }

            // Causal mask (only the diagonal tile needs it)
            if (kt == qt) {
                const int r0 = warp * 16 + g, r1 = r0 + 8;
                #pragma unroll
                for (int nt = 0; nt < 8; nt++) {
                    int c0 = nt * 8 + 2 * t, c1 = c0 + 1;
                    if (c0 > r0) sc[nt][0] = -INFINITY;
                    if (c1 > r0) sc[nt][1] = -INFINITY;
                    if (c0 > r1) sc[nt][2] = -INFINITY;
                    if (c1 > r1) sc[nt][3] = -INFINITY;
                }
            }

            // Online softmax (rows g and g+8; reduce across quad lanes)
            float tm0 = -INFINITY, tm1 = -INFINITY;
            #pragma unroll
            for (int nt = 0; nt < 8; nt++) {
                tm0 = fmaxf(tm0, fmaxf(sc[nt][0], sc[nt][1]));
                tm1 = fmaxf(tm1, fmaxf(sc[nt][2], sc[nt][3]));
            }
            tm0 = fmaxf(tm0, __shfl_xor_sync(0xffffffffu, tm0, 1));
            tm0 = fmaxf(tm0, __shfl_xor_sync(0xffffffffu, tm0, 2));
            tm1 = fmaxf(tm1, __shfl_xor_sync(0xffffffffu, tm1, 1));
            tm1 = fmaxf(tm1, __shfl_xor_sync(0xffffffffu, tm1, 2));

            const float m0n = fmaxf(m0, tm0), m1n = fmaxf(m1, tm1);
            const float cs0 = __expf(m0 - m0n), cs1 = __expf(m1 - m1n);
            l0 *= cs0; l1 *= cs1;
            #pragma unroll
            for (int nt = 0; nt < 8; nt++) {
                o[nt][0] *= cs0; o[nt][1] *= cs0;
                o[nt][2] *= cs1; o[nt][3] *= cs1;
            }
            m0 = m0n; m1 = m1n;

            #pragma unroll
            for (int nt = 0; nt < 8; nt++) {
                float p0 = __expf(sc[nt][0] - m0);
                float p1 = __expf(sc[nt][1] - m0);
                float p2 = __expf(sc[nt][2] - m1);
                float p3 = __expf(sc[nt][3] - m1);
                l0 += p0 + p1; l1 += p2 + p3;
                Pw[g * KTS + nt * 8 + 2 * t]           = f2tf(p0);
                Pw[g * KTS + nt * 8 + 2 * t + 1]       = f2tf(p1);
                Pw[(g + 8) * KTS + nt * 8 + 2 * t]     = f2tf(p2);
                Pw[(g + 8) * KTS + nt * 8 + 2 * t + 1] = f2tf(p3);
            }
            __syncwarp();

            // O += P @ V
            #pragma unroll
            for (int kc = 0; kc < 8; kc++) {
                uint32_t a0 = __float_as_uint(Pw[g * KTS + kc * 8 + t]);
                uint32_t a1 = __float_as_uint(Pw[(g + 8) * KTS + kc * 8 + t]);
                uint32_t a2 = __float_as_uint(Pw[g * KTS + kc * 8 + t + 4]);
                uint32_t a3 = __float_as_uint(Pw[(g + 8) * KTS + kc * 8 + t + 4]);
                const float* vb0 = Vs + (kc * 8 + t) * KTS + g;
                const float* vb1 = Vs + (kc * 8 + t + 4) * KTS + g;
                #pragma unroll
                for (int nt = 0; nt < 8; nt++) {
                    mma_tf32(o[nt], a0, a1, a2, a3,
                             __float_as_uint(vb0[nt * 8]),
                             __float_as_uint(vb1[nt * 8]));
                }
            }
        } // kt

        l0 += __shfl_xor_sync(0xffffffffu, l0, 1);
        l0 += __shfl_xor_sync(0xffffffffu, l0, 2);
        l1 += __shfl_xor_sync(0xffffffffu, l1, 1);
        l1 += __shfl_xor_sync(0xffffffffu, l1, 2);
        const float i0 = 1.0f / l0, i1 = 1.0f / l1;

        float* ob = O + (tok0 + qrow) * DMODEL + h * HD;
        #pragma unroll
        for (int nt = 0; nt < 8; nt++) {
            *(float2*)(ob + nt * 8 + 2 * t) =
                make_float2(o[nt][0] * i0, o[nt][1] * i0);
            *(float2*)(ob + 8 * DMODEL + nt * 8 + 2 * t) =
                make_float2(o[nt][2] * i1, o[nt][3] * i1);
        }
    } // pass
}

// ---------------------------------------------------------------------------
// Launch
// ---------------------------------------------------------------------------
extern "C" void kernel_launch(void* const* d_in, const int* in_sizes, int n_in,
                              void* d_out, int out_size)
{
    const float* x   = (const float*)d_in[0];
    const float* W_q = (const float*)d_in[1];
    const float* W_k = (const float*)d_in[2];
    const float* W_v = (const float*)d_in[3];
    const float* W_o = (const float*)d_in[4];
    float* out = (float*)d_out;

    float *Qp, *Kp, *Vp, *Ap;
    cudaGetSymbolAddress((void**)&Qp, g_Q);
    cudaGetSymbolAddress((void**)&Kp, g_K);
    cudaGetSymbolAddress((void**)&Vp, g_V);
    cudaGetSymbolAddress((void**)&Ap, g_A);

    cudaFuncSetAttribute(gemm_tf32, cudaFuncAttributeMaxDynamicSharedMemorySize, GEMM_SMEM);
    cudaFuncSetAttribute(attn_mma, cudaFuncAttributeMaxDynamicSharedMemorySize, ATTN_SMEM);

    dim3 ggrd(DMODEL / BN, NT / BM);   // (8, 32)

    gemm_tf32<<<ggrd, 256, GEMM_SMEM>>>(x, W_q, Qp, NT, DMODEL, DMODEL);
    gemm_tf32<<<ggrd, 256, GEMM_SMEM>>>(x, W_k, Kp, NT, DMODEL, DMODEL);
    gemm_tf32<<<ggrd, 256, GEMM_SMEM>>>(x, W_v, Vp, NT, DMODEL, DMODEL);

    dim3 agrd(16, NHEAD, BATCH);       // q-tile pairs (bx, 31-bx)
    attn_mma<<<agrd, 128, ATTN_SMEM>>>(Qp, Kp, Vp, Ap);

    gemm_tf32<<<ggrd, 256, GEMM_SMEM>>>(Ap, W_o, out, NT, DMODEL, DMODEL);
}